// round 2
// baseline (speedup 1.0000x reference)
#include <cuda_runtime.h>
#include <math.h>

#define Bsz 4
#define Lq  1024
#define Dm  1024
#define NH  16
#define HD  64

// ---------------- scratch (static device globals; no allocation) ----------------
__device__ float g_q[Bsz * Lq * Dm];       // 16 MB
__device__ float g_k[Bsz * Lq * Dm];       // 16 MB
__device__ float g_v[Bsz * Lq * Dm];       // 16 MB
__device__ float g_ctx[Bsz * Lq * Dm];     // 16 MB
__device__ float g_scores[(size_t)Bsz * NH * Lq * Lq];   // 256 MB
__device__ float g_wt[4 * 3 * Dm * Dm];    // 48 MB: [sel][t][i][o]
__device__ int   g_mask_is_word;

// ---------------- mask dtype detection ----------------
// int32 0/1 mask: first 4096 bytes -> ~512 nonzero bytes. bool/int8 mask:
// ~2048 nonzero. float32 0/1 mask: ~1024 nonzero -> "word" path also reads it
// correctly (nonzero bits for 1.0f).
__global__ void detect_mask(const unsigned char* __restrict__ m) {
    __shared__ int red[256];
    int tid = threadIdx.x;
    int c = 0;
    for (int i = tid; i < 4096; i += 256) c += (m[i] != 0);
    red[tid] = c;
    __syncthreads();
    for (int s = 128; s > 0; s >>= 1) {
        if (tid < s) red[tid] += red[tid + s];
        __syncthreads();
    }
    if (tid == 0) g_mask_is_word = (red[0] < 1536) ? 1 : 0;
}

// ---------------- weight transpose: w[o][i][t] -> wt[t][i][o] ----------------
// Treat w as a [1024 x 3072] matrix (row o, col c = i*3+t). Tiled transpose:
// reads coalesced in c, writes coalesced in o.
__global__ void transpose_w(const float* __restrict__ w, int wsel) {
    __shared__ float tile[32][33];
    int c0 = blockIdx.x * 32;   // over 3072
    int o0 = blockIdx.y * 32;   // over 1024
    int tx = threadIdx.x, ty = threadIdx.y;   // 32 x 8
#pragma unroll
    for (int r = 0; r < 32; r += 8)
        tile[ty + r][tx] = w[(size_t)(o0 + ty + r) * (3 * Dm) + c0 + tx];
    __syncthreads();
    float* wt = g_wt + (size_t)wsel * 3 * Dm * Dm;
#pragma unroll
    for (int r = 0; r < 32; r += 8) {
        int c = c0 + ty + r;
        int i = c / 3;
        int t = c - i * 3;
        // FIX: transposed read tile[tx][ty+r] = w[o0+tx][c0+ty+r]
        wt[(size_t)t * Dm * Dm + (size_t)i * Dm + o0 + tx] = tile[tx][ty + r];
    }
}

// ---------------- conv1d as shifted GEMM ----------------
// y[b,l,o] = bias[o] + sum_t sum_i x[b, l+t-1, i] * wt[t][i][o]
// Tile 128x128, BK=16, 256 threads, 8x8 per thread.
__global__ __launch_bounds__(256) void conv_gemm(
    const float* __restrict__ xin, const float* __restrict__ bias,
    float* __restrict__ yext, int wsel, int xsel, int ysel)
{
    const float* x = (xsel == 0) ? xin : g_ctx;
    float* y;
    if (ysel == 0)      y = g_q;
    else if (ysel == 1) y = g_k;
    else if (ysel == 2) y = g_v;
    else                y = yext;
    const float* wt = g_wt + (size_t)wsel * 3 * Dm * Dm;

    int rowTile = blockIdx.y * 128;          // global b*L + l tile (aligned in batch)
    int colTile = blockIdx.x * 128;
    int b = rowTile / Lq;
    int lbase = rowTile - b * Lq;
    const float* xb = x + (size_t)b * Lq * Dm;

    __shared__ float As[16][132];
    __shared__ float Bs[16][132];

    float acc[8][8];
#pragma unroll
    for (int i = 0; i < 8; i++)
#pragma unroll
        for (int j = 0; j < 8; j++) acc[i][j] = 0.f;

    int tid = threadIdx.x;
    int tr = tid >> 4, tc = tid & 15;
    int aRow = tid >> 2;            // 0..63
    int aK4  = (tid & 3) << 2;      // 0,4,8,12
    int bK   = tid >> 5;            // 0..7
    int bN4  = (tid & 31) << 2;     // 0..124

    for (int t = 0; t < 3; ++t) {
        const float* wtt = wt + (size_t)t * Dm * Dm;
        int shift = t - 1;
        for (int kk = 0; kk < Dm; kk += 16) {
#pragma unroll
            for (int rr = 0; rr < 2; ++rr) {
                int row = aRow + rr * 64;
                int l = lbase + row + shift;
                float4 v = make_float4(0.f, 0.f, 0.f, 0.f);
                if (l >= 0 && l < Lq)
                    v = *reinterpret_cast<const float4*>(xb + (size_t)l * Dm + kk + aK4);
                As[aK4 + 0][row] = v.x;
                As[aK4 + 1][row] = v.y;
                As[aK4 + 2][row] = v.z;
                As[aK4 + 3][row] = v.w;
            }
#pragma unroll
            for (int rr = 0; rr < 2; ++rr) {
                int k = bK + rr * 8;
                float4 v = *reinterpret_cast<const float4*>(
                    wtt + (size_t)(kk + k) * Dm + colTile + bN4);
                Bs[k][bN4 + 0] = v.x;
                Bs[k][bN4 + 1] = v.y;
                Bs[k][bN4 + 2] = v.z;
                Bs[k][bN4 + 3] = v.w;
            }
            __syncthreads();
#pragma unroll
            for (int k = 0; k < 16; ++k) {
                float ra[8], rb[8];
#pragma unroll
                for (int i = 0; i < 8; i++) ra[i] = As[k][tr * 8 + i];
#pragma unroll
                for (int j = 0; j < 8; j++) rb[j] = Bs[k][tc * 8 + j];
#pragma unroll
                for (int i = 0; i < 8; i++)
#pragma unroll
                    for (int j = 0; j < 8; j++) acc[i][j] += ra[i] * rb[j];
            }
            __syncthreads();
        }
    }
#pragma unroll
    for (int i = 0; i < 8; i++) {
        int r = rowTile + tr * 8 + i;
#pragma unroll
        for (int j = 0; j < 8; j++) {
            int c = colTile + tc * 8 + j;
            y[(size_t)r * Dm + c] = acc[i][j] + bias[c];
        }
    }
}

// ---------------- scores: S = Q K^T * scale + attn_mask, padding mask -> -inf ----
__global__ __launch_bounds__(256) void scores_gemm(
    const float* __restrict__ am, const void* __restrict__ kpm)
{
    int bh = blockIdx.z;
    int b = bh >> 4;
    int h = bh & 15;
    int i0 = blockIdx.y * 128;
    int j0 = blockIdx.x * 128;
    const float* qb = g_q + (size_t)b * Lq * Dm + h * HD;
    const float* kb = g_k + (size_t)b * Lq * Dm + h * HD;

    __shared__ float As[16][132];
    __shared__ float Bs[16][132];

    float acc[8][8];
#pragma unroll
    for (int i = 0; i < 8; i++)
#pragma unroll
        for (int j = 0; j < 8; j++) acc[i][j] = 0.f;

    int tid = threadIdx.x;
    int tr = tid >> 4, tc = tid & 15;
    int aRow = tid >> 2;
    int aK4  = (tid & 3) << 2;

    for (int kk = 0; kk < HD; kk += 16) {
#pragma unroll
        for (int rr = 0; rr < 2; ++rr) {
            int row = aRow + rr * 64;
            float4 v = *reinterpret_cast<const float4*>(
                qb + (size_t)(i0 + row) * Dm + kk + aK4);
            As[aK4 + 0][row] = v.x;
            As[aK4 + 1][row] = v.y;
            As[aK4 + 2][row] = v.z;
            As[aK4 + 3][row] = v.w;
            float4 w = *reinterpret_cast<const float4*>(
                kb + (size_t)(j0 + row) * Dm + kk + aK4);
            Bs[aK4 + 0][row] = w.x;
            Bs[aK4 + 1][row] = w.y;
            Bs[aK4 + 2][row] = w.z;
            Bs[aK4 + 3][row] = w.w;
        }
        __syncthreads();
#pragma unroll
        for (int k = 0; k < 16; ++k) {
            float ra[8], rb[8];
#pragma unroll
            for (int i = 0; i < 8; i++) ra[i] = As[k][tr * 8 + i];
#pragma unroll
            for (int j = 0; j < 8; j++) rb[j] = Bs[k][tc * 8 + j];
#pragma unroll
            for (int i = 0; i < 8; i++)
#pragma unroll
                for (int j = 0; j < 8; j++) acc[i][j] += ra[i] * rb[j];
        }
        __syncthreads();
    }

    int mword = g_mask_is_word;
    bool mk[8];
#pragma unroll
    for (int j = 0; j < 8; j++) {
        int gj = j0 + tc * 8 + j;
        mk[j] = mword ? (((const int*)kpm)[b * Lq + gj] != 0)
                      : (((const unsigned char*)kpm)[b * Lq + gj] != 0);
    }
    float* srow = g_scores + (size_t)bh * Lq * Lq;
    const float scale = 0.125f;   // 64^-0.5
#pragma unroll
    for (int i = 0; i < 8; i++) {
        int gi = i0 + tr * 8 + i;
#pragma unroll
        for (int j = 0; j < 8; j++) {
            int gj = j0 + tc * 8 + j;
            float v = acc[i][j] * scale + am[(size_t)gi * Lq + gj];
            srow[(size_t)gi * Lq + gj] = mk[j] ? -INFINITY : v;
        }
    }
}

// ---------------- row softmax over L=1024 ----------------
__global__ __launch_bounds__(256) void softmax_rows() {
    size_t row = blockIdx.x;
    float* p = g_scores + row * Lq;
    int tid = threadIdx.x;
    __shared__ float red[256];

    float v[4];
    float m = -INFINITY;
#pragma unroll
    for (int c = 0; c < 4; c++) {
        v[c] = p[tid + c * 256];
        m = fmaxf(m, v[c]);
    }
    red[tid] = m;
    __syncthreads();
    for (int s = 128; s > 0; s >>= 1) {
        if (tid < s) red[tid] = fmaxf(red[tid], red[tid + s]);
        __syncthreads();
    }
    m = red[0];
    __syncthreads();

    float sum = 0.f;
#pragma unroll
    for (int c = 0; c < 4; c++) {
        v[c] = expf(v[c] - m);
        sum += v[c];
    }
    red[tid] = sum;
    __syncthreads();
    for (int s = 128; s > 0; s >>= 1) {
        if (tid < s) red[tid] += red[tid + s];
        __syncthreads();
    }
    float inv = 1.f / red[0];
#pragma unroll
    for (int c = 0; c < 4; c++) p[tid + c * 256] = v[c] * inv;
}

// ---------------- PV: ctx = attn @ V_head (128x64 tile, BK=16) ----------------
__global__ __launch_bounds__(256) void pv_gemm() {
    int bh = blockIdx.y;
    int b = bh >> 4;
    int h = bh & 15;
    int i0 = blockIdx.x * 128;
    const float* att = g_scores + (size_t)bh * Lq * Lq;
    const float* vb = g_v + (size_t)b * Lq * Dm + h * HD;
    float* cb = g_ctx + (size_t)b * Lq * Dm + h * HD;

    __shared__ float As[16][132];
    __shared__ float Bs[16][68];

    float acc[8][4];
#pragma unroll
    for (int i = 0; i < 8; i++)
#pragma unroll
        for (int j = 0; j < 4; j++) acc[i][j] = 0.f;

    int tid = threadIdx.x;
    int tr = tid >> 4, tc = tid & 15;
    int aRow = tid >> 2;
    int aK4  = (tid & 3) << 2;
    int bK   = tid >> 4;           // 0..15
    int bD4  = (tid & 15) << 2;    // 0..60

    for (int kk = 0; kk < Lq; kk += 16) {
#pragma unroll
        for (int rr = 0; rr < 2; ++rr) {
            int row = aRow + rr * 64;
            float4 v = *reinterpret_cast<const float4*>(
                att + (size_t)(i0 + row) * Lq + kk + aK4);
            As[aK4 + 0][row] = v.x;
            As[aK4 + 1][row] = v.y;
            As[aK4 + 2][row] = v.z;
            As[aK4 + 3][row] = v.w;
        }
        {
            float4 w = *reinterpret_cast<const float4*>(
                vb + (size_t)(kk + bK) * Dm + bD4);
            Bs[bK][bD4 + 0] = w.x;
            Bs[bK][bD4 + 1] = w.y;
            Bs[bK][bD4 + 2] = w.z;
            Bs[bK][bD4 + 3] = w.w;
        }
        __syncthreads();
#pragma unroll
        for (int k = 0; k < 16; ++k) {
            float ra[8], rb[4];
#pragma unroll
            for (int i = 0; i < 8; i++) ra[i] = As[k][tr * 8 + i];
#pragma unroll
            for (int j = 0; j < 4; j++) rb[j] = Bs[k][tc * 4 + j];
#pragma unroll
            for (int i = 0; i < 8; i++)
#pragma unroll
                for (int j = 0; j < 4; j++) acc[i][j] += ra[i] * rb[j];
        }
        __syncthreads();
    }
#pragma unroll
    for (int i = 0; i < 8; i++) {
        int gi = i0 + tr * 8 + i;
#pragma unroll
        for (int j = 0; j < 4; j++)
            cb[(size_t)gi * Dm + tc * 4 + j] = acc[i][j];
    }
}

// ---------------- launch ----------------
extern "C" void kernel_launch(void* const* d_in, const int* in_sizes, int n_in,
                              void* d_out, int out_size) {
    // Robust input classification by element count (order within a size class
    // is preserved): 4194304 -> q,k,v; 4096 -> key_padding_mask;
    // 1048576 -> attn_mask; 3145728 -> q_w,k_w,v_w,o_w; 1024 -> biases.
    const float* qkv[3] = {nullptr, nullptr, nullptr};
    const float* ws[4]  = {nullptr, nullptr, nullptr, nullptr};
    const float* bs[4]  = {nullptr, nullptr, nullptr, nullptr};
    const void*  kpm = nullptr;
    const float* am  = nullptr;
    int nqkv = 0, nw = 0, nb = 0;
    for (int i = 0; i < n_in; ++i) {
        int sz = in_sizes[i];
        if (sz == Bsz * Lq * Dm)           { if (nqkv < 3) qkv[nqkv++] = (const float*)d_in[i]; }
        else if (sz == 3 * Dm * Dm)        { if (nw < 4)   ws[nw++]    = (const float*)d_in[i]; }
        else if (sz == Dm)                 { if (nb < 4)   bs[nb++]    = (const float*)d_in[i]; }
        else if (sz == Bsz * Lq)           { kpm = d_in[i]; }
        else if (sz == Lq * Lq)            { am  = (const float*)d_in[i]; }
    }
    float* out = (float*)d_out;

    detect_mask<<<1, 256>>>((const unsigned char*)kpm);

    dim3 tb(32, 8);
    dim3 tg(3 * Dm / 32, Dm / 32);
    transpose_w<<<tg, tb>>>(ws[0], 0);
    transpose_w<<<tg, tb>>>(ws[1], 1);
    transpose_w<<<tg, tb>>>(ws[2], 2);
    transpose_w<<<tg, tb>>>(ws[3], 3);

    dim3 cg(Dm / 128, Bsz * Lq / 128);    // (8, 32)
    conv_gemm<<<cg, 256>>>(qkv[0], bs[0], nullptr, 0, 0, 0);
    conv_gemm<<<cg, 256>>>(qkv[1], bs[1], nullptr, 1, 0, 1);
    conv_gemm<<<cg, 256>>>(qkv[2], bs[2], nullptr, 2, 0, 2);

    scores_gemm<<<dim3(Lq / 128, Lq / 128, Bsz * NH), 256>>>(am, kpm);
    softmax_rows<<<Bsz * NH * Lq, 256>>>();
    pv_gemm<<<dim3(Lq / 128, Bsz * NH), 256>>>();

    conv_gemm<<<cg, 256>>>(nullptr, bs[3], out, 3, 1, 3);
}

// round 4
// speedup vs baseline: 1.5227x; 1.5227x over previous
#include <cuda_runtime.h>
#include <cuda_bf16.h>
#include <math.h>
#include <stdint.h>

#define Bsz 4
#define Lq  1024
#define Dm  1024
#define NH  16
#define HD  64

// ---------------- scratch (static device globals; no allocation) ----------------
__device__ float g_q[Bsz * Lq * Dm];
__device__ float g_k[Bsz * Lq * Dm];
__device__ float g_v[Bsz * Lq * Dm];
__device__ float g_ctx[Bsz * Lq * Dm];
__device__ float g_scores[(size_t)Bsz * NH * Lq * Lq];   // 256 MB
__device__ int   g_mask_is_word;

// bf16 split operands for tensor-core conv GEMMs
__device__ __align__(256) __nv_bfloat16 g_xhi[Bsz * Lq * Dm];
__device__ __align__(256) __nv_bfloat16 g_xlo[Bsz * Lq * Dm];
__device__ __align__(256) __nv_bfloat16 g_whi[4][3 * Dm * Dm];  // [sel][t][o][i]
__device__ __align__(256) __nv_bfloat16 g_wlo[4][3 * Dm * Dm];

// ================= warp-MMA helpers (plain compute_103-safe PTX) =================
__device__ __forceinline__ uint32_t smem_u32(const void* p) {
    uint32_t a;
    asm("{ .reg .u64 t; cvta.to.shared.u64 t, %1; cvt.u32.u64 %0, t; }"
        : "=r"(a) : "l"(p));
    return a;
}
__device__ __forceinline__ void ldsm_x4(uint32_t* r, uint32_t addr) {
    asm volatile("ldmatrix.sync.aligned.m8n8.x4.shared.b16 {%0,%1,%2,%3}, [%4];"
                 : "=r"(r[0]), "=r"(r[1]), "=r"(r[2]), "=r"(r[3]) : "r"(addr));
}
__device__ __forceinline__ void mma16816(float* c, const uint32_t* a,
                                          const uint32_t b0, const uint32_t b1) {
    asm volatile(
        "mma.sync.aligned.m16n8k16.row.col.f32.bf16.bf16.f32 "
        "{%0,%1,%2,%3}, {%4,%5,%6,%7}, {%8,%9}, {%0,%1,%2,%3};"
        : "+f"(c[0]), "+f"(c[1]), "+f"(c[2]), "+f"(c[3])
        : "r"(a[0]), "r"(a[1]), "r"(a[2]), "r"(a[3]), "r"(b0), "r"(b1));
}

// ---------------- mask dtype detection ----------------
__global__ void detect_mask(const unsigned char* __restrict__ m) {
    __shared__ int red[256];
    int tid = threadIdx.x;
    int c = 0;
    for (int i = tid; i < 4096; i += 256) c += (m[i] != 0);
    red[tid] = c;
    __syncthreads();
    for (int s = 128; s > 0; s >>= 1) {
        if (tid < s) red[tid] += red[tid + s];
        __syncthreads();
    }
    if (tid == 0) g_mask_is_word = (red[0] < 1536) ? 1 : 0;
}

// ---------------- bf16 split preps ----------------
__device__ __forceinline__ void split_bf16(float x, __nv_bfloat16& h, __nv_bfloat16& l) {
    h = __float2bfloat16_rn(x);
    l = __float2bfloat16_rn(x - __bfloat162float(h));
}

__global__ void prep_x(const float* __restrict__ src_ext, int use_ctx) {
    const float* src = use_ctx ? g_ctx : src_ext;
    int idx = blockIdx.x * blockDim.x + threadIdx.x;   // per 4 floats
    float4 v = reinterpret_cast<const float4*>(src)[idx];
    __nv_bfloat16 h0, l0, h1, l1, h2, l2, h3, l3;
    split_bf16(v.x, h0, l0); split_bf16(v.y, h1, l1);
    split_bf16(v.z, h2, l2); split_bf16(v.w, h3, l3);
    __nv_bfloat162 hi01(h0, h1), hi23(h2, h3), lo01(l0, l1), lo23(l2, l3);
    reinterpret_cast<__nv_bfloat162*>(g_xhi)[idx * 2 + 0] = hi01;
    reinterpret_cast<__nv_bfloat162*>(g_xhi)[idx * 2 + 1] = hi23;
    reinterpret_cast<__nv_bfloat162*>(g_xlo)[idx * 2 + 0] = lo01;
    reinterpret_cast<__nv_bfloat162*>(g_xlo)[idx * 2 + 1] = lo23;
}

// w[o][i][t] -> whi/wlo[sel][t][o][i]
__global__ void prep_w(const float* __restrict__ w, int sel) {
    int j = blockIdx.x * blockDim.x + threadIdx.x;    // over 3*1024*1024
    int t = j >> 20;
    int rem = j & 0xFFFFF;
    int o = rem >> 10;
    int i = rem & 1023;
    float v = w[((size_t)o * Dm + i) * 3 + t];
    __nv_bfloat16 h, l;
    split_bf16(v, h, l);
    g_whi[sel][j] = h;
    g_wlo[sel][j] = l;
}

// ---------------- conv1d GEMM on tensor cores (mma.sync bf16 split) ----------------
// Block: 128 threads = 4 warps. Block tile 128(m) x 64(n). Warp tile 64x32.
// y[m,o] = bias[o] + sum_{t,i} x[b, l+t-1, i] * w[o,i,t]
#define SSTR 40   // smem row stride in bf16 (80B: conflict-free for ldmatrix)

__global__ __launch_bounds__(128, 3) void conv_mma(
    const float* __restrict__ bias, float* __restrict__ yext, int wsel, int ysel)
{
    __shared__ __nv_bfloat16 sAhi[128][SSTR];
    __shared__ __nv_bfloat16 sAlo[128][SSTR];
    __shared__ __nv_bfloat16 sBhi[64][SSTR];
    __shared__ __nv_bfloat16 sBlo[64][SSTR];

    float* y;
    if (ysel == 0)      y = g_q;
    else if (ysel == 1) y = g_k;
    else if (ysel == 2) y = g_v;
    else                y = yext;

    const __nv_bfloat16* whi = g_whi[wsel];
    const __nv_bfloat16* wlo = g_wlo[wsel];

    int tid = threadIdx.x;
    int lane = tid & 31;
    int w = tid >> 5;
    int wm = (w >> 1) * 64;     // warp m offset in block tile
    int wn = (w & 1) * 32;      // warp n offset

    int colTile = blockIdx.x * 64;
    int rowTile = blockIdx.y * 128;
    int b = rowTile >> 10;
    int lbase = rowTile & 1023;

    float acc[4][4][4];
#pragma unroll
    for (int mt = 0; mt < 4; mt++)
#pragma unroll
        for (int nt = 0; nt < 4; nt++)
#pragma unroll
            for (int r = 0; r < 4; r++) acc[mt][nt][r] = 0.f;

    // ldmatrix per-lane row/col-half (same for A tiles and B tile-pairs)
    int lrow = lane & 15;
    int lhalf = (lane >> 4) * 8;

    uint32_t sAhi_b = smem_u32(&sAhi[0][0]);
    uint32_t sAlo_b = smem_u32(&sAlo[0][0]);
    uint32_t sBhi_b = smem_u32(&sBhi[0][0]);
    uint32_t sBlo_b = smem_u32(&sBlo[0][0]);

    for (int t = 0; t < 3; ++t) {
        int shift = t - 1;
        const __nv_bfloat16* whit = whi + ((size_t)t << 20);
        const __nv_bfloat16* wlot = wlo + ((size_t)t << 20);
        for (int k0 = 0; k0 < Dm; k0 += 32) {
            __syncthreads();
            // ---- stage A: 128 rows x 32 cols (hi+lo), 512 uint4 each ----
#pragma unroll
            for (int vv = 0; vv < 4; ++vv) {
                int v = tid + vv * 128;            // 0..511
                int row = v >> 2;
                int c8 = (v & 3) << 3;             // bf16 col
                int l = lbase + row + shift;
                uint4 hv = make_uint4(0, 0, 0, 0), lv = make_uint4(0, 0, 0, 0);
                if (l >= 0 && l < Lq) {
                    size_t g = ((size_t)(b << 10) + l) * Dm + k0 + c8;
                    hv = *reinterpret_cast<const uint4*>(g_xhi + g);
                    lv = *reinterpret_cast<const uint4*>(g_xlo + g);
                }
                *reinterpret_cast<uint4*>(&sAhi[row][c8]) = hv;
                *reinterpret_cast<uint4*>(&sAlo[row][c8]) = lv;
            }
            // ---- stage B: 64 rows x 32 cols (hi+lo), 256 uint4 each ----
#pragma unroll
            for (int vv = 0; vv < 2; ++vv) {
                int v = tid + vv * 128;            // 0..255
                int row = v >> 2;
                int c8 = (v & 3) << 3;
                size_t gw = (size_t)(colTile + row) * Dm + k0 + c8;
                *reinterpret_cast<uint4*>(&sBhi[row][c8]) =
                    *reinterpret_cast<const uint4*>(whit + gw);
                *reinterpret_cast<uint4*>(&sBlo[row][c8]) =
                    *reinterpret_cast<const uint4*>(wlot + gw);
            }
            __syncthreads();

            // ---- compute: 2 k16 steps ----
#pragma unroll
            for (int ks = 0; ks < 32; ks += 16) {
                uint32_t a_hi[4][4], a_lo[4][4];
#pragma unroll
                for (int mt = 0; mt < 4; mt++) {
                    uint32_t off = (uint32_t)((wm + mt * 16 + lrow) * SSTR + ks + lhalf) * 2;
                    ldsm_x4(a_hi[mt], sAhi_b + off);
                    ldsm_x4(a_lo[mt], sAlo_b + off);
                }
                uint32_t b_hi[4][2], b_lo[4][2];
#pragma unroll
                for (int p = 0; p < 2; p++) {
                    uint32_t off = (uint32_t)((wn + p * 16 + lrow) * SSTR + ks + lhalf) * 2;
                    uint32_t q[4];
                    ldsm_x4(q, sBhi_b + off);
                    b_hi[2 * p][0] = q[0]; b_hi[2 * p][1] = q[2];
                    b_hi[2 * p + 1][0] = q[1]; b_hi[2 * p + 1][1] = q[3];
                    ldsm_x4(q, sBlo_b + off);
                    b_lo[2 * p][0] = q[0]; b_lo[2 * p][1] = q[2];
                    b_lo[2 * p + 1][0] = q[1]; b_lo[2 * p + 1][1] = q[3];
                }
#pragma unroll
                for (int mt = 0; mt < 4; mt++)
#pragma unroll
                    for (int nt = 0; nt < 4; nt++) {
                        mma16816(acc[mt][nt], a_hi[mt], b_hi[nt][0], b_hi[nt][1]);
                        mma16816(acc[mt][nt], a_hi[mt], b_lo[nt][0], b_lo[nt][1]);
                        mma16816(acc[mt][nt], a_lo[mt], b_hi[nt][0], b_hi[nt][1]);
                    }
            }
        }
    }

    // ---- epilogue: acc -> y + bias ----
#pragma unroll
    for (int nt = 0; nt < 4; nt++) {
        int n0 = colTile + wn + nt * 8 + (lane & 3) * 2;
        float b0 = bias[n0], b1 = bias[n0 + 1];
#pragma unroll
        for (int mt = 0; mt < 4; mt++) {
            int m0 = rowTile + wm + mt * 16 + (lane >> 2);
            float* c = acc[mt][nt];
            float2 v0 = make_float2(c[0] + b0, c[1] + b1);
            float2 v1 = make_float2(c[2] + b0, c[3] + b1);
            *reinterpret_cast<float2*>(y + (size_t)m0 * Dm + n0) = v0;
            *reinterpret_cast<float2*>(y + (size_t)(m0 + 8) * Dm + n0) = v1;
        }
    }
}

// ---------------- scores: S = Q K^T * scale + attn_mask, padding mask -> -inf ----
__global__ __launch_bounds__(256) void scores_gemm(
    const float* __restrict__ am, const void* __restrict__ kpm)
{
    int bh = blockIdx.z;
    int b = bh >> 4;
    int h = bh & 15;
    int i0 = blockIdx.y * 128;
    int j0 = blockIdx.x * 128;
    const float* qb = g_q + (size_t)b * Lq * Dm + h * HD;
    const float* kb = g_k + (size_t)b * Lq * Dm + h * HD;

    __shared__ float As[16][132];
    __shared__ float Bs[16][132];

    float acc[8][8];
#pragma unroll
    for (int i = 0; i < 8; i++)
#pragma unroll
        for (int j = 0; j < 8; j++) acc[i][j] = 0.f;

    int tid = threadIdx.x;
    int tr = tid >> 4, tc = tid & 15;
    int aRow = tid >> 2;
    int aK4  = (tid & 3) << 2;

    for (int kk = 0; kk < HD; kk += 16) {
#pragma unroll
        for (int rr = 0; rr < 2; ++rr) {
            int row = aRow + rr * 64;
            float4 v = *reinterpret_cast<const float4*>(
                qb + (size_t)(i0 + row) * Dm + kk + aK4);
            As[aK4 + 0][row] = v.x;
            As[aK4 + 1][row] = v.y;
            As[aK4 + 2][row] = v.z;
            As[aK4 + 3][row] = v.w;
            float4 w = *reinterpret_cast<const float4*>(
                kb + (size_t)(j0 + row) * Dm + kk + aK4);
            Bs[aK4 + 0][row] = w.x;
            Bs[aK4 + 1][row] = w.y;
            Bs[aK4 + 2][row] = w.z;
            Bs[aK4 + 3][row] = w.w;
        }
        __syncthreads();
#pragma unroll
        for (int k = 0; k < 16; ++k) {
            float ra[8], rb[8];
#pragma unroll
            for (int i = 0; i < 8; i++) ra[i] = As[k][tr * 8 + i];
#pragma unroll
            for (int j = 0; j < 8; j++) rb[j] = Bs[k][tc * 8 + j];
#pragma unroll
            for (int i = 0; i < 8; i++)
#pragma unroll
                for (int j = 0; j < 8; j++) acc[i][j] += ra[i] * rb[j];
        }
        __syncthreads();
    }

    int mword = g_mask_is_word;
    bool mk[8];
#pragma unroll
    for (int j = 0; j < 8; j++) {
        int gj = j0 + tc * 8 + j;
        mk[j] = mword ? (((const int*)kpm)[b * Lq + gj] != 0)
                      : (((const unsigned char*)kpm)[b * Lq + gj] != 0);
    }
    float* srow = g_scores + (size_t)bh * Lq * Lq;
    const float scale = 0.125f;
#pragma unroll
    for (int i = 0; i < 8; i++) {
        int gi = i0 + tr * 8 + i;
#pragma unroll
        for (int j = 0; j < 8; j++) {
            int gj = j0 + tc * 8 + j;
            float v = acc[i][j] * scale + am[(size_t)gi * Lq + gj];
            srow[(size_t)gi * Lq + gj] = mk[j] ? -INFINITY : v;
        }
    }
}

// ---------------- row softmax over L=1024 ----------------
__global__ __launch_bounds__(256) void softmax_rows() {
    size_t row = blockIdx.x;
    float* p = g_scores + row * Lq;
    int tid = threadIdx.x;
    __shared__ float red[256];

    float v[4];
    float m = -INFINITY;
#pragma unroll
    for (int c = 0; c < 4; c++) {
        v[c] = p[tid + c * 256];
        m = fmaxf(m, v[c]);
    }
    red[tid] = m;
    __syncthreads();
    for (int s = 128; s > 0; s >>= 1) {
        if (tid < s) red[tid] = fmaxf(red[tid], red[tid + s]);
        __syncthreads();
    }
    m = red[0];
    __syncthreads();

    float sum = 0.f;
#pragma unroll
    for (int c = 0; c < 4; c++) {
        v[c] = expf(v[c] - m);
        sum += v[c];
    }
    red[tid] = sum;
    __syncthreads();
    for (int s = 128; s > 0; s >>= 1) {
        if (tid < s) red[tid] += red[tid + s];
        __syncthreads();
    }
    float inv = 1.f / red[0];
#pragma unroll
    for (int c = 0; c < 4; c++) p[tid + c * 256] = v[c] * inv;
}

// ---------------- PV: ctx = attn @ V_head (128x64 tile, BK=16) ----------------
__global__ __launch_bounds__(256) void pv_gemm() {
    int bh = blockIdx.y;
    int b = bh >> 4;
    int h = bh & 15;
    int i0 = blockIdx.x * 128;
    const float* att = g_scores + (size_t)bh * Lq * Lq;
    const float* vb = g_v + (size_t)b * Lq * Dm + h * HD;
    float* cb = g_ctx + (size_t)b * Lq * Dm + h * HD;

    __shared__ float As[16][132];
    __shared__ float Bs[16][68];

    float acc[8][4];
#pragma unroll
    for (int i = 0; i < 8; i++)
#pragma unroll
        for (int j = 0; j < 4; j++) acc[i][j] = 0.f;

    int tid = threadIdx.x;
    int tr = tid >> 4, tc = tid & 15;
    int aRow = tid >> 2;
    int aK4  = (tid & 3) << 2;
    int bK   = tid >> 4;
    int bD4  = (tid & 15) << 2;

    for (int kk = 0; kk < Lq; kk += 16) {
#pragma unroll
        for (int rr = 0; rr < 2; ++rr) {
            int row = aRow + rr * 64;
            float4 v = *reinterpret_cast<const float4*>(
                att + (size_t)(i0 + row) * Lq + kk + aK4);
            As[aK4 + 0][row] = v.x;
            As[aK4 + 1][row] = v.y;
            As[aK4 + 2][row] = v.z;
            As[aK4 + 3][row] = v.w;
        }
        {
            float4 w = *reinterpret_cast<const float4*>(
                vb + (size_t)(kk + bK) * Dm + bD4);
            Bs[bK][bD4 + 0] = w.x;
            Bs[bK][bD4 + 1] = w.y;
            Bs[bK][bD4 + 2] = w.z;
            Bs[bK][bD4 + 3] = w.w;
        }
        __syncthreads();
#pragma unroll
        for (int k = 0; k < 16; ++k) {
            float ra[8], rb[4];
#pragma unroll
            for (int i = 0; i < 8; i++) ra[i] = As[k][tr * 8 + i];
#pragma unroll
            for (int j = 0; j < 4; j++) rb[j] = Bs[k][tc * 4 + j];
#pragma unroll
            for (int i = 0; i < 8; i++)
#pragma unroll
                for (int j = 0; j < 4; j++) acc[i][j] += ra[i] * rb[j];
        }
        __syncthreads();
    }
#pragma unroll
    for (int i = 0; i < 8; i++) {
        int gi = i0 + tr * 8 + i;
#pragma unroll
        for (int j = 0; j < 4; j++)
            cb[(size_t)gi * Dm + tc * 4 + j] = acc[i][j];
    }
}

// ---------------- launch ----------------
extern "C" void kernel_launch(void* const* d_in, const int* in_sizes, int n_in,
                              void* d_out, int out_size) {
    const float* qkv[3] = {nullptr, nullptr, nullptr};
    const float* ws[4]  = {nullptr, nullptr, nullptr, nullptr};
    const float* bs[4]  = {nullptr, nullptr, nullptr, nullptr};
    const void*  kpm = nullptr;
    const float* am  = nullptr;
    int nqkv = 0, nw = 0, nb = 0;
    for (int i = 0; i < n_in; ++i) {
        int sz = in_sizes[i];
        if (sz == Bsz * Lq * Dm)           { if (nqkv < 3) qkv[nqkv++] = (const float*)d_in[i]; }
        else if (sz == 3 * Dm * Dm)        { if (nw < 4)   ws[nw++]    = (const float*)d_in[i]; }
        else if (sz == Dm)                 { if (nb < 4)   bs[nb++]    = (const float*)d_in[i]; }
        else if (sz == Bsz * Lq)           { kpm = d_in[i]; }
        else if (sz == Lq * Lq)            { am  = (const float*)d_in[i]; }
    }
    float* out = (float*)d_out;

    detect_mask<<<1, 256>>>((const unsigned char*)kpm);

    for (int s = 0; s < 4; ++s)
        prep_w<<<3 * Dm * Dm / 256, 256>>>(ws[s], s);

    dim3 cg(Dm / 64, Bsz * Lq / 128);     // (16, 32)
    const int PX_GRID = Bsz * Lq * Dm / 4 / 256;

    prep_x<<<PX_GRID, 256>>>(qkv[0], 0);
    conv_mma<<<cg, 128>>>(bs[0], nullptr, 0, 0);
    prep_x<<<PX_GRID, 256>>>(qkv[1], 0);
    conv_mma<<<cg, 128>>>(bs[1], nullptr, 1, 1);
    prep_x<<<PX_GRID, 256>>>(qkv[2], 0);
    conv_mma<<<cg, 128>>>(bs[2], nullptr, 2, 2);

    scores_gemm<<<dim3(Lq / 128, Lq / 128, Bsz * NH), 256>>>(am, kpm);
    softmax_rows<<<Bsz * NH * Lq, 256>>>();
    pv_gemm<<<dim3(Lq / 128, Bsz * NH), 256>>>();

    prep_x<<<PX_GRID, 256>>>(nullptr, 1);
    conv_mma<<<cg, 128>>>(bs[3], out, 3, 3);
}

// round 5
// speedup vs baseline: 1.9163x; 1.2585x over previous
#include <cuda_runtime.h>
#include <cuda_bf16.h>
#include <math.h>
#include <stdint.h>

#define Bsz 4
#define Lq  1024
#define Dm  1024
#define NH  16
#define HD  64

// ---------------- scratch (static device globals; no allocation) ----------------
__device__ float g_ctx[Bsz * Lq * Dm];                    // 16 MB
__device__ float g_scores[(size_t)Bsz * NH * Lq * Lq];    // 256 MB
__device__ int   g_mask_is_word;

// bf16 split operands
__device__ __align__(256) __nv_bfloat16 g_xhi[Bsz * Lq * Dm];
__device__ __align__(256) __nv_bfloat16 g_xlo[Bsz * Lq * Dm];
__device__ __align__(256) __nv_bfloat16 g_whi[4][3 * Dm * Dm];  // [sel][t][o][i]
__device__ __align__(256) __nv_bfloat16 g_wlo[4][3 * Dm * Dm];
__device__ __align__(256) __nv_bfloat16 g_qhi[Bsz * Lq * Dm];
__device__ __align__(256) __nv_bfloat16 g_qlo[Bsz * Lq * Dm];
__device__ __align__(256) __nv_bfloat16 g_khi[Bsz * Lq * Dm];
__device__ __align__(256) __nv_bfloat16 g_klo[Bsz * Lq * Dm];
__device__ __align__(256) __nv_bfloat16 g_vhi[Bsz * Lq * Dm];
__device__ __align__(256) __nv_bfloat16 g_vlo[Bsz * Lq * Dm];
__device__ __align__(256) __nv_bfloat16 g_phi[(size_t)Bsz * NH * Lq * Lq];  // 128 MB
__device__ __align__(256) __nv_bfloat16 g_plo[(size_t)Bsz * NH * Lq * Lq];  // 128 MB

// ================= warp-MMA helpers (plain compute_103-safe PTX) =================
__device__ __forceinline__ uint32_t smem_u32(const void* p) {
    uint32_t a;
    asm("{ .reg .u64 t; cvta.to.shared.u64 t, %1; cvt.u32.u64 %0, t; }"
        : "=r"(a) : "l"(p));
    return a;
}
__device__ __forceinline__ void ldsm_x4(uint32_t* r, uint32_t addr) {
    asm volatile("ldmatrix.sync.aligned.m8n8.x4.shared.b16 {%0,%1,%2,%3}, [%4];"
                 : "=r"(r[0]), "=r"(r[1]), "=r"(r[2]), "=r"(r[3]) : "r"(addr));
}
__device__ __forceinline__ void ldsm_x4_t(uint32_t* r, uint32_t addr) {
    asm volatile("ldmatrix.sync.aligned.m8n8.x4.trans.shared.b16 {%0,%1,%2,%3}, [%4];"
                 : "=r"(r[0]), "=r"(r[1]), "=r"(r[2]), "=r"(r[3]) : "r"(addr));
}
__device__ __forceinline__ void mma16816(float* c, const uint32_t* a,
                                          const uint32_t b0, const uint32_t b1) {
    asm volatile(
        "mma.sync.aligned.m16n8k16.row.col.f32.bf16.bf16.f32 "
        "{%0,%1,%2,%3}, {%4,%5,%6,%7}, {%8,%9}, {%0,%1,%2,%3};"
        : "+f"(c[0]), "+f"(c[1]), "+f"(c[2]), "+f"(c[3])
        : "r"(a[0]), "r"(a[1]), "r"(a[2]), "r"(a[3]), "r"(b0), "r"(b1));
}

// ---------------- mask dtype detection ----------------
__global__ void detect_mask(const unsigned char* __restrict__ m) {
    __shared__ int red[256];
    int tid = threadIdx.x;
    int c = 0;
    for (int i = tid; i < 4096; i += 256) c += (m[i] != 0);
    red[tid] = c;
    __syncthreads();
    for (int s = 128; s > 0; s >>= 1) {
        if (tid < s) red[tid] += red[tid + s];
        __syncthreads();
    }
    if (tid == 0) g_mask_is_word = (red[0] < 1536) ? 1 : 0;
}

// ---------------- bf16 split preps ----------------
__device__ __forceinline__ void split_bf16(float x, __nv_bfloat16& h, __nv_bfloat16& l) {
    h = __float2bfloat16_rn(x);
    l = __float2bfloat16_rn(x - __bfloat162float(h));
}

__global__ void prep_x(const float* __restrict__ src_ext, int use_ctx) {
    const float* src = use_ctx ? g_ctx : src_ext;
    int idx = blockIdx.x * blockDim.x + threadIdx.x;
    float4 v = reinterpret_cast<const float4*>(src)[idx];
    __nv_bfloat16 h0, l0, h1, l1, h2, l2, h3, l3;
    split_bf16(v.x, h0, l0); split_bf16(v.y, h1, l1);
    split_bf16(v.z, h2, l2); split_bf16(v.w, h3, l3);
    reinterpret_cast<__nv_bfloat162*>(g_xhi)[idx * 2 + 0] = __nv_bfloat162(h0, h1);
    reinterpret_cast<__nv_bfloat162*>(g_xhi)[idx * 2 + 1] = __nv_bfloat162(h2, h3);
    reinterpret_cast<__nv_bfloat162*>(g_xlo)[idx * 2 + 0] = __nv_bfloat162(l0, l1);
    reinterpret_cast<__nv_bfloat162*>(g_xlo)[idx * 2 + 1] = __nv_bfloat162(l2, l3);
}

// w[o][i][t] -> whi/wlo[sel][t][o][i]
__global__ void prep_w(const float* __restrict__ w, int sel) {
    int j = blockIdx.x * blockDim.x + threadIdx.x;
    int t = j >> 20;
    int rem = j & 0xFFFFF;
    int o = rem >> 10;
    int i = rem & 1023;
    float v = w[((size_t)o * Dm + i) * 3 + t];
    __nv_bfloat16 h, l;
    split_bf16(v, h, l);
    g_whi[sel][j] = h;
    g_wlo[sel][j] = l;
}

// ---------------- conv1d GEMM on tensor cores (mma.sync bf16 split) ----------------
#define SSTR 40

__global__ __launch_bounds__(128, 3) void conv_mma(
    const float* __restrict__ bias, float* __restrict__ yext, int wsel, int ysel)
{
    __shared__ __nv_bfloat16 sAhi[128][SSTR];
    __shared__ __nv_bfloat16 sAlo[128][SSTR];
    __shared__ __nv_bfloat16 sBhi[64][SSTR];
    __shared__ __nv_bfloat16 sBlo[64][SSTR];

    const __nv_bfloat16* whi = g_whi[wsel];
    const __nv_bfloat16* wlo = g_wlo[wsel];

    int tid = threadIdx.x;
    int lane = tid & 31;
    int w = tid >> 5;
    int wm = (w >> 1) * 64;
    int wn = (w & 1) * 32;

    int colTile = blockIdx.x * 64;
    int rowTile = blockIdx.y * 128;
    int b = rowTile >> 10;
    int lbase = rowTile & 1023;

    float acc[4][4][4];
#pragma unroll
    for (int mt = 0; mt < 4; mt++)
#pragma unroll
        for (int nt = 0; nt < 4; nt++)
#pragma unroll
            for (int r = 0; r < 4; r++) acc[mt][nt][r] = 0.f;

    int lrow = lane & 15;
    int lhalf = (lane >> 4) * 8;

    uint32_t sAhi_b = smem_u32(&sAhi[0][0]);
    uint32_t sAlo_b = smem_u32(&sAlo[0][0]);
    uint32_t sBhi_b = smem_u32(&sBhi[0][0]);
    uint32_t sBlo_b = smem_u32(&sBlo[0][0]);

    for (int t = 0; t < 3; ++t) {
        int shift = t - 1;
        const __nv_bfloat16* whit = whi + ((size_t)t << 20);
        const __nv_bfloat16* wlot = wlo + ((size_t)t << 20);
        for (int k0 = 0; k0 < Dm; k0 += 32) {
            __syncthreads();
#pragma unroll
            for (int vv = 0; vv < 4; ++vv) {
                int v = tid + vv * 128;
                int row = v >> 2;
                int c8 = (v & 3) << 3;
                int l = lbase + row + shift;
                uint4 hv = make_uint4(0, 0, 0, 0), lv = make_uint4(0, 0, 0, 0);
                if (l >= 0 && l < Lq) {
                    size_t g = ((size_t)(b << 10) + l) * Dm + k0 + c8;
                    hv = *reinterpret_cast<const uint4*>(g_xhi + g);
                    lv = *reinterpret_cast<const uint4*>(g_xlo + g);
                }
                *reinterpret_cast<uint4*>(&sAhi[row][c8]) = hv;
                *reinterpret_cast<uint4*>(&sAlo[row][c8]) = lv;
            }
#pragma unroll
            for (int vv = 0; vv < 2; ++vv) {
                int v = tid + vv * 128;
                int row = v >> 2;
                int c8 = (v & 3) << 3;
                size_t gw = (size_t)(colTile + row) * Dm + k0 + c8;
                *reinterpret_cast<uint4*>(&sBhi[row][c8]) =
                    *reinterpret_cast<const uint4*>(whit + gw);
                *reinterpret_cast<uint4*>(&sBlo[row][c8]) =
                    *reinterpret_cast<const uint4*>(wlot + gw);
            }
            __syncthreads();

#pragma unroll
            for (int ks = 0; ks < 32; ks += 16) {
                uint32_t a_hi[4][4], a_lo[4][4];
#pragma unroll
                for (int mt = 0; mt < 4; mt++) {
                    uint32_t off = (uint32_t)((wm + mt * 16 + lrow) * SSTR + ks + lhalf) * 2;
                    ldsm_x4(a_hi[mt], sAhi_b + off);
                    ldsm_x4(a_lo[mt], sAlo_b + off);
                }
                uint32_t b_hi[4][2], b_lo[4][2];
#pragma unroll
                for (int p = 0; p < 2; p++) {
                    uint32_t off = (uint32_t)((wn + p * 16 + lrow) * SSTR + ks + lhalf) * 2;
                    uint32_t q[4];
                    ldsm_x4(q, sBhi_b + off);
                    b_hi[2 * p][0] = q[0]; b_hi[2 * p][1] = q[2];
                    b_hi[2 * p + 1][0] = q[1]; b_hi[2 * p + 1][1] = q[3];
                    ldsm_x4(q, sBlo_b + off);
                    b_lo[2 * p][0] = q[0]; b_lo[2 * p][1] = q[2];
                    b_lo[2 * p + 1][0] = q[1]; b_lo[2 * p + 1][1] = q[3];
                }
#pragma unroll
                for (int mt = 0; mt < 4; mt++)
#pragma unroll
                    for (int nt = 0; nt < 4; nt++) {
                        mma16816(acc[mt][nt], a_hi[mt], b_hi[nt][0], b_hi[nt][1]);
                        mma16816(acc[mt][nt], a_hi[mt], b_lo[nt][0], b_lo[nt][1]);
                        mma16816(acc[mt][nt], a_lo[mt], b_hi[nt][0], b_hi[nt][1]);
                    }
            }
        }
    }

    // ---- epilogue ----
    if (ysel < 3) {
        __nv_bfloat16 *yh, *yl;
        if (ysel == 0)      { yh = g_qhi; yl = g_qlo; }
        else if (ysel == 1) { yh = g_khi; yl = g_klo; }
        else                { yh = g_vhi; yl = g_vlo; }
#pragma unroll
        for (int nt = 0; nt < 4; nt++) {
            int n0 = colTile + wn + nt * 8 + (lane & 3) * 2;
            float b0 = bias[n0], b1 = bias[n0 + 1];
#pragma unroll
            for (int mt = 0; mt < 4; mt++) {
                int m0 = rowTile + wm + mt * 16 + (lane >> 2);
                float* c = acc[mt][nt];
                __nv_bfloat16 h0, l0, h1, l1;
                split_bf16(c[0] + b0, h0, l0);
                split_bf16(c[1] + b1, h1, l1);
                *reinterpret_cast<__nv_bfloat162*>(yh + (size_t)m0 * Dm + n0) = __nv_bfloat162(h0, h1);
                *reinterpret_cast<__nv_bfloat162*>(yl + (size_t)m0 * Dm + n0) = __nv_bfloat162(l0, l1);
                split_bf16(c[2] + b0, h0, l0);
                split_bf16(c[3] + b1, h1, l1);
                *reinterpret_cast<__nv_bfloat162*>(yh + (size_t)(m0 + 8) * Dm + n0) = __nv_bfloat162(h0, h1);
                *reinterpret_cast<__nv_bfloat162*>(yl + (size_t)(m0 + 8) * Dm + n0) = __nv_bfloat162(l0, l1);
            }
        }
    } else {
#pragma unroll
        for (int nt = 0; nt < 4; nt++) {
            int n0 = colTile + wn + nt * 8 + (lane & 3) * 2;
            float b0 = bias[n0], b1 = bias[n0 + 1];
#pragma unroll
            for (int mt = 0; mt < 4; mt++) {
                int m0 = rowTile + wm + mt * 16 + (lane >> 2);
                float* c = acc[mt][nt];
                *reinterpret_cast<float2*>(yext + (size_t)m0 * Dm + n0) =
                    make_float2(c[0] + b0, c[1] + b1);
                *reinterpret_cast<float2*>(yext + (size_t)(m0 + 8) * Dm + n0) =
                    make_float2(c[2] + b0, c[3] + b1);
            }
        }
    }
}

// ---------------- scores on tensor cores ----------------
// Block 128 threads / 4 warps; tile 128(i) x 128(j); K=64 in two 32-chunks.
__global__ __launch_bounds__(128) void scores_mma(
    const float* __restrict__ am, const void* __restrict__ kpm)
{
    __shared__ __nv_bfloat16 sQh[128][SSTR];
    __shared__ __nv_bfloat16 sQl[128][SSTR];
    __shared__ __nv_bfloat16 sKh[128][SSTR];
    __shared__ __nv_bfloat16 sKl[128][SSTR];

    int bh = blockIdx.z, b = bh >> 4, h = bh & 15;
    int i0 = blockIdx.y * 128, j0 = blockIdx.x * 128;
    const __nv_bfloat16* qh = g_qhi + ((size_t)(b << 10) + i0) * Dm + h * HD;
    const __nv_bfloat16* ql = g_qlo + ((size_t)(b << 10) + i0) * Dm + h * HD;
    const __nv_bfloat16* kh = g_khi + ((size_t)(b << 10) + j0) * Dm + h * HD;
    const __nv_bfloat16* kl = g_klo + ((size_t)(b << 10) + j0) * Dm + h * HD;

    int tid = threadIdx.x, lane = tid & 31, w = tid >> 5;
    int wm = (w >> 1) * 64, wn = (w & 1) * 64;
    int lrow = lane & 15, lhalf = (lane >> 4) * 8;

    float acc[4][8][4];
#pragma unroll
    for (int mt = 0; mt < 4; mt++)
#pragma unroll
        for (int nt = 0; nt < 8; nt++)
#pragma unroll
            for (int r = 0; r < 4; r++) acc[mt][nt][r] = 0.f;

    uint32_t bQh = smem_u32(&sQh[0][0]), bQl = smem_u32(&sQl[0][0]);
    uint32_t bKh = smem_u32(&sKh[0][0]), bKl = smem_u32(&sKl[0][0]);

    for (int k0 = 0; k0 < HD; k0 += 32) {
        __syncthreads();
#pragma unroll
        for (int vv = 0; vv < 4; ++vv) {
            int v = tid + vv * 128;
            int row = v >> 2;
            int c8 = (v & 3) << 3;
            size_t off = (size_t)row * Dm + k0 + c8;
            *reinterpret_cast<uint4*>(&sQh[row][c8]) = *reinterpret_cast<const uint4*>(qh + off);
            *reinterpret_cast<uint4*>(&sQl[row][c8]) = *reinterpret_cast<const uint4*>(ql + off);
            *reinterpret_cast<uint4*>(&sKh[row][c8]) = *reinterpret_cast<const uint4*>(kh + off);
            *reinterpret_cast<uint4*>(&sKl[row][c8]) = *reinterpret_cast<const uint4*>(kl + off);
        }
        __syncthreads();

#pragma unroll
        for (int ks = 0; ks < 32; ks += 16) {
            uint32_t ah[4][4], al[4][4];
#pragma unroll
            for (int mt = 0; mt < 4; mt++) {
                uint32_t off = (uint32_t)((wm + mt * 16 + lrow) * SSTR + ks + lhalf) * 2;
                ldsm_x4(ah[mt], bQh + off);
                ldsm_x4(al[mt], bQl + off);
            }
#pragma unroll
            for (int p = 0; p < 4; p++) {
                uint32_t off = (uint32_t)((wn + p * 16 + lrow) * SSTR + ks + lhalf) * 2;
                uint32_t kh4[4], kl4[4];
                ldsm_x4(kh4, bKh + off);
                ldsm_x4(kl4, bKl + off);
#pragma unroll
                for (int mt = 0; mt < 4; mt++) {
                    mma16816(acc[mt][2 * p],     ah[mt], kh4[0], kh4[2]);
                    mma16816(acc[mt][2 * p],     ah[mt], kl4[0], kl4[2]);
                    mma16816(acc[mt][2 * p],     al[mt], kh4[0], kh4[2]);
                    mma16816(acc[mt][2 * p + 1], ah[mt], kh4[1], kh4[3]);
                    mma16816(acc[mt][2 * p + 1], ah[mt], kl4[1], kl4[3]);
                    mma16816(acc[mt][2 * p + 1], al[mt], kh4[1], kh4[3]);
                }
            }
        }
    }

    int mword = g_mask_is_word;
    float* srow = g_scores + (size_t)bh * Lq * Lq;
    const float scale = 0.125f;
#pragma unroll
    for (int nt = 0; nt < 8; nt++) {
        int n0 = j0 + wn + nt * 8 + (lane & 3) * 2;
        bool mk0 = mword ? (((const int*)kpm)[b * Lq + n0] != 0)
                         : (((const unsigned char*)kpm)[b * Lq + n0] != 0);
        bool mk1 = mword ? (((const int*)kpm)[b * Lq + n0 + 1] != 0)
                         : (((const unsigned char*)kpm)[b * Lq + n0 + 1] != 0);
#pragma unroll
        for (int mt = 0; mt < 4; mt++) {
            float* c = acc[mt][nt];
            int m0 = i0 + wm + mt * 16 + (lane >> 2);
            float2 a0 = *reinterpret_cast<const float2*>(am + (size_t)m0 * Lq + n0);
            *reinterpret_cast<float2*>(srow + (size_t)m0 * Lq + n0) =
                make_float2(mk0 ? -INFINITY : c[0] * scale + a0.x,
                            mk1 ? -INFINITY : c[1] * scale + a0.y);
            int m1 = m0 + 8;
            float2 a1 = *reinterpret_cast<const float2*>(am + (size_t)m1 * Lq + n0);
            *reinterpret_cast<float2*>(srow + (size_t)m1 * Lq + n0) =
                make_float2(mk0 ? -INFINITY : c[2] * scale + a1.x,
                            mk1 ? -INFINITY : c[3] * scale + a1.y);
        }
    }
}

// ---------------- row softmax -> split bf16 attn ----------------
__global__ __launch_bounds__(256) void softmax_rows() {
    size_t row = blockIdx.x;
    const float* p = g_scores + row * Lq;
    __nv_bfloat16* ph = g_phi + row * Lq;
    __nv_bfloat16* pl = g_plo + row * Lq;
    int tid = threadIdx.x;
    __shared__ float red[256];

    float v[4];
    float m = -INFINITY;
#pragma unroll
    for (int c = 0; c < 4; c++) {
        v[c] = p[tid + c * 256];
        m = fmaxf(m, v[c]);
    }
    red[tid] = m;
    __syncthreads();
    for (int s = 128; s > 0; s >>= 1) {
        if (tid < s) red[tid] = fmaxf(red[tid], red[tid + s]);
        __syncthreads();
    }
    m = red[0];
    __syncthreads();

    float sum = 0.f;
#pragma unroll
    for (int c = 0; c < 4; c++) {
        v[c] = expf(v[c] - m);
        sum += v[c];
    }
    red[tid] = sum;
    __syncthreads();
    for (int s = 128; s > 0; s >>= 1) {
        if (tid < s) red[tid] += red[tid + s];
        __syncthreads();
    }
    float inv = 1.f / red[0];
#pragma unroll
    for (int c = 0; c < 4; c++) {
        float pv = v[c] * inv;
        __nv_bfloat16 h, l;
        split_bf16(pv, h, l);
        ph[tid + c * 256] = h;
        pl[tid + c * 256] = l;
    }
}

// ---------------- PV on tensor cores ----------------
// Block 128 threads / 4 warps; tile 128(i) x 64(d); K=1024 in 32-chunks.
// V is [l][d] (n-contiguous) -> B-frag via ldmatrix.trans.
#define VSTR 72

__global__ __launch_bounds__(128) void pv_mma() {
    __shared__ __nv_bfloat16 sPh[128][SSTR];
    __shared__ __nv_bfloat16 sPl[128][SSTR];
    __shared__ __nv_bfloat16 sVh[32][VSTR];
    __shared__ __nv_bfloat16 sVl[32][VSTR];

    int bh = blockIdx.y, b = bh >> 4, h = bh & 15;
    int i0 = blockIdx.x * 128;
    const __nv_bfloat16* ph = g_phi + ((size_t)bh * Lq + i0) * Lq;
    const __nv_bfloat16* pl = g_plo + ((size_t)bh * Lq + i0) * Lq;
    const __nv_bfloat16* vh = g_vhi + ((size_t)(b << 10)) * Dm + h * HD;
    const __nv_bfloat16* vl = g_vlo + ((size_t)(b << 10)) * Dm + h * HD;

    int tid = threadIdx.x, lane = tid & 31, w = tid >> 5;
    int wm = (w >> 1) * 64, wn = (w & 1) * 32;
    int lrow = lane & 15, lhalf = (lane >> 4) * 8;

    float acc[4][4][4];
#pragma unroll
    for (int mt = 0; mt < 4; mt++)
#pragma unroll
        for (int nt = 0; nt < 4; nt++)
#pragma unroll
            for (int r = 0; r < 4; r++) acc[mt][nt][r] = 0.f;

    uint32_t bPh = smem_u32(&sPh[0][0]), bPl = smem_u32(&sPl[0][0]);
    uint32_t bVh = smem_u32(&sVh[0][0]), bVl = smem_u32(&sVl[0][0]);

    for (int k0 = 0; k0 < Lq; k0 += 32) {
        __syncthreads();
#pragma unroll
        for (int vv = 0; vv < 4; ++vv) {
            int v = tid + vv * 128;
            int row = v >> 2;
            int c8 = (v & 3) << 3;
            size_t off = (size_t)row * Lq + k0 + c8;
            *reinterpret_cast<uint4*>(&sPh[row][c8]) = *reinterpret_cast<const uint4*>(ph + off);
            *reinterpret_cast<uint4*>(&sPl[row][c8]) = *reinterpret_cast<const uint4*>(pl + off);
        }
#pragma unroll
        for (int vv = 0; vv < 2; ++vv) {
            int v = tid + vv * 128;
            int row = v >> 3;
            int c8 = (v & 7) << 3;
            size_t off = (size_t)(k0 + row) * Dm + c8;
            *reinterpret_cast<uint4*>(&sVh[row][c8]) = *reinterpret_cast<const uint4*>(vh + off);
            *reinterpret_cast<uint4*>(&sVl[row][c8]) = *reinterpret_cast<const uint4*>(vl + off);
        }
        __syncthreads();

#pragma unroll
        for (int ks = 0; ks < 32; ks += 16) {
            uint32_t ah[4][4], al[4][4];
#pragma unroll
            for (int mt = 0; mt < 4; mt++) {
                uint32_t off = (uint32_t)((wm + mt * 16 + lrow) * SSTR + ks + lhalf) * 2;
                ldsm_x4(ah[mt], bPh + off);
                ldsm_x4(al[mt], bPl + off);
            }
#pragma unroll
            for (int p = 0; p < 2; p++) {
                // trans: rows over k (lrow), col half over n (lhalf)
                uint32_t off = (uint32_t)((ks + lrow) * VSTR + wn + p * 16 + lhalf) * 2;
                uint32_t vh4[4], vl4[4];
                ldsm_x4_t(vh4, bVh + off);
                ldsm_x4_t(vl4, bVl + off);
#pragma unroll
                for (int mt = 0; mt < 4; mt++) {
                    mma16816(acc[mt][2 * p],     ah[mt], vh4[0], vh4[1]);
                    mma16816(acc[mt][2 * p],     ah[mt], vl4[0], vl4[1]);
                    mma16816(acc[mt][2 * p],     al[mt], vh4[0], vh4[1]);
                    mma16816(acc[mt][2 * p + 1], ah[mt], vh4[2], vh4[3]);
                    mma16816(acc[mt][2 * p + 1], ah[mt], vl4[2], vl4[3]);
                    mma16816(acc[mt][2 * p + 1], al[mt], vh4[2], vh4[3]);
                }
            }
        }
    }

    float* cb = g_ctx + ((size_t)(b << 10)) * Dm + h * HD;
#pragma unroll
    for (int nt = 0; nt < 4; nt++) {
        int n0 = wn + nt * 8 + (lane & 3) * 2;
#pragma unroll
        for (int mt = 0; mt < 4; mt++) {
            int m0 = i0 + wm + mt * 16 + (lane >> 2);
            float* c = acc[mt][nt];
            *reinterpret_cast<float2*>(cb + (size_t)m0 * Dm + n0) = make_float2(c[0], c[1]);
            *reinterpret_cast<float2*>(cb + (size_t)(m0 + 8) * Dm + n0) = make_float2(c[2], c[3]);
        }
    }
}

// ---------------- launch ----------------
extern "C" void kernel_launch(void* const* d_in, const int* in_sizes, int n_in,
                              void* d_out, int out_size) {
    const float* qkv[3] = {nullptr, nullptr, nullptr};
    const float* ws[4]  = {nullptr, nullptr, nullptr, nullptr};
    const float* bs[4]  = {nullptr, nullptr, nullptr, nullptr};
    const void*  kpm = nullptr;
    const float* am  = nullptr;
    int nqkv = 0, nw = 0, nb = 0;
    for (int i = 0; i < n_in; ++i) {
        int sz = in_sizes[i];
        if (sz == Bsz * Lq * Dm)           { if (nqkv < 3) qkv[nqkv++] = (const float*)d_in[i]; }
        else if (sz == 3 * Dm * Dm)        { if (nw < 4)   ws[nw++]    = (const float*)d_in[i]; }
        else if (sz == Dm)                 { if (nb < 4)   bs[nb++]    = (const float*)d_in[i]; }
        else if (sz == Bsz * Lq)           { kpm = d_in[i]; }
        else if (sz == Lq * Lq)            { am  = (const float*)d_in[i]; }
    }
    float* out = (float*)d_out;

    detect_mask<<<1, 256>>>((const unsigned char*)kpm);

    for (int s = 0; s < 4; ++s)
        prep_w<<<3 * Dm * Dm / 256, 256>>>(ws[s], s);

    dim3 cg(Dm / 64, Bsz * Lq / 128);     // (16, 32)
    const int PX_GRID = Bsz * Lq * Dm / 4 / 256;

    prep_x<<<PX_GRID, 256>>>(qkv[0], 0);
    conv_mma<<<cg, 128>>>(bs[0], nullptr, 0, 0);
    prep_x<<<PX_GRID, 256>>>(qkv[1], 0);
    conv_mma<<<cg, 128>>>(bs[1], nullptr, 1, 1);
    prep_x<<<PX_GRID, 256>>>(qkv[2], 0);
    conv_mma<<<cg, 128>>>(bs[2], nullptr, 2, 2);

    scores_mma<<<dim3(Lq / 128, Lq / 128, Bsz * NH), 128>>>(am, kpm);
    softmax_rows<<<Bsz * NH * Lq, 256>>>();
    pv_mma<<<dim3(Lq / 128, Bsz * NH), 128>>>();

    prep_x<<<PX_GRID, 256>>>(nullptr, 1);
    conv_mma<<<cg, 128>>>(bs[3], out, 3, 3);
}

// round 6
// speedup vs baseline: 2.1949x; 1.1454x over previous
#include <cuda_runtime.h>
#include <cuda_bf16.h>
#include <math.h>
#include <stdint.h>

#define Bsz 4
#define Lq  1024
#define Dm  1024
#define NH  16
#define HD  64

// ---------------- scratch (static device globals; no allocation) ----------------
__device__ float g_ctx[Bsz * Lq * Dm];                    // 16 MB
__device__ float g_scores[(size_t)Bsz * NH * Lq * Lq];    // 256 MB
__device__ int   g_mask_is_word;

// bf16 split operands
__device__ __align__(256) __nv_bfloat16 g_xhi[Bsz * Lq * Dm];
__device__ __align__(256) __nv_bfloat16 g_xlo[Bsz * Lq * Dm];
__device__ __align__(256) __nv_bfloat16 g_whi[4][3 * Dm * Dm];  // [sel][t][o][i]
__device__ __align__(256) __nv_bfloat16 g_wlo[4][3 * Dm * Dm];
__device__ __align__(256) __nv_bfloat16 g_qhi[Bsz * Lq * Dm];
__device__ __align__(256) __nv_bfloat16 g_qlo[Bsz * Lq * Dm];
__device__ __align__(256) __nv_bfloat16 g_khi[Bsz * Lq * Dm];
__device__ __align__(256) __nv_bfloat16 g_klo[Bsz * Lq * Dm];
__device__ __align__(256) __nv_bfloat16 g_vhi[Bsz * Lq * Dm];
__device__ __align__(256) __nv_bfloat16 g_vlo[Bsz * Lq * Dm];
__device__ __align__(256) __nv_bfloat16 g_phi[(size_t)Bsz * NH * Lq * Lq];  // 128 MB
__device__ __align__(256) __nv_bfloat16 g_plo[(size_t)Bsz * NH * Lq * Lq];  // 128 MB

// ================= warp-MMA helpers (plain compute_103-safe PTX) =================
__device__ __forceinline__ uint32_t smem_u32(const void* p) {
    uint32_t a;
    asm("{ .reg .u64 t; cvta.to.shared.u64 t, %1; cvt.u32.u64 %0, t; }"
        : "=r"(a) : "l"(p));
    return a;
}
__device__ __forceinline__ void ldsm_x4(uint32_t* r, uint32_t addr) {
    asm volatile("ldmatrix.sync.aligned.m8n8.x4.shared.b16 {%0,%1,%2,%3}, [%4];"
                 : "=r"(r[0]), "=r"(r[1]), "=r"(r[2]), "=r"(r[3]) : "r"(addr));
}
__device__ __forceinline__ void ldsm_x4_t(uint32_t* r, uint32_t addr) {
    asm volatile("ldmatrix.sync.aligned.m8n8.x4.trans.shared.b16 {%0,%1,%2,%3}, [%4];"
                 : "=r"(r[0]), "=r"(r[1]), "=r"(r[2]), "=r"(r[3]) : "r"(addr));
}
__device__ __forceinline__ void mma16816(float* c, const uint32_t* a,
                                          const uint32_t b0, const uint32_t b1) {
    asm volatile(
        "mma.sync.aligned.m16n8k16.row.col.f32.bf16.bf16.f32 "
        "{%0,%1,%2,%3}, {%4,%5,%6,%7}, {%8,%9}, {%0,%1,%2,%3};"
        : "+f"(c[0]), "+f"(c[1]), "+f"(c[2]), "+f"(c[3])
        : "r"(a[0]), "r"(a[1]), "r"(a[2]), "r"(a[3]), "r"(b0), "r"(b1));
}
__device__ __forceinline__ void cp_async16(uint32_t dst, const void* src, int src_bytes) {
    asm volatile("cp.async.cg.shared.global [%0], [%1], 16, %2;"
                 :: "r"(dst), "l"(src), "r"(src_bytes) : "memory");
}
#define CP_COMMIT() asm volatile("cp.async.commit_group;" ::: "memory")
#define CP_WAIT1()  asm volatile("cp.async.wait_group 1;" ::: "memory")

// ---------------- mask dtype detection ----------------
__global__ void detect_mask(const unsigned char* __restrict__ m) {
    __shared__ int red[256];
    int tid = threadIdx.x;
    int c = 0;
    for (int i = tid; i < 4096; i += 256) c += (m[i] != 0);
    red[tid] = c;
    __syncthreads();
    for (int s = 128; s > 0; s >>= 1) {
        if (tid < s) red[tid] += red[tid + s];
        __syncthreads();
    }
    if (tid == 0) g_mask_is_word = (red[0] < 1536) ? 1 : 0;
}

// ---------------- bf16 split preps ----------------
__device__ __forceinline__ void split_bf16(float x, __nv_bfloat16& h, __nv_bfloat16& l) {
    h = __float2bfloat16_rn(x);
    l = __float2bfloat16_rn(x - __bfloat162float(h));
}

__global__ void prep_x(const float* __restrict__ src_ext, int use_ctx) {
    const float* src = use_ctx ? g_ctx : src_ext;
    int idx = blockIdx.x * blockDim.x + threadIdx.x;
    float4 v = reinterpret_cast<const float4*>(src)[idx];
    __nv_bfloat16 h0, l0, h1, l1, h2, l2, h3, l3;
    split_bf16(v.x, h0, l0); split_bf16(v.y, h1, l1);
    split_bf16(v.z, h2, l2); split_bf16(v.w, h3, l3);
    reinterpret_cast<__nv_bfloat162*>(g_xhi)[idx * 2 + 0] = __nv_bfloat162(h0, h1);
    reinterpret_cast<__nv_bfloat162*>(g_xhi)[idx * 2 + 1] = __nv_bfloat162(h2, h3);
    reinterpret_cast<__nv_bfloat162*>(g_xlo)[idx * 2 + 0] = __nv_bfloat162(l0, l1);
    reinterpret_cast<__nv_bfloat162*>(g_xlo)[idx * 2 + 1] = __nv_bfloat162(l2, l3);
}

// w[o][i][t] -> whi/wlo[sel][t][o][i]
__global__ void prep_w(const float* __restrict__ w, int sel) {
    int j = blockIdx.x * blockDim.x + threadIdx.x;
    int t = j >> 20;
    int rem = j & 0xFFFFF;
    int o = rem >> 10;
    int i = rem & 1023;
    float v = w[((size_t)o * Dm + i) * 3 + t];
    __nv_bfloat16 h, l;
    split_bf16(v, h, l);
    g_whi[sel][j] = h;
    g_wlo[sel][j] = l;
}

// ---------------- conv1d GEMM, pipelined (cp.async double buffer) ----------------
// Block 128 threads / 4 warps; tile 128(m) x 64(n); K chunks of 32.
// A buffer holds 130 rows (128 + halo) so all 3 taps share one staging pass.
#define SSTR 40
#define A_ROWS 130
#define A_MAT (A_ROWS * SSTR)    // bf16 per A matrix
#define B_MAT (64 * SSTR)
#define CONV_SMEM ((4 * A_MAT + 4 * B_MAT) * 2)   // bytes

__global__ __launch_bounds__(128, 3) void conv_mma(
    const float* __restrict__ bias, float* __restrict__ yext, int wsel, int ysel)
{
    extern __shared__ __nv_bfloat16 sm[];

    int tid = threadIdx.x;
    int lane = tid & 31;
    int w = tid >> 5;
    int wm = (w >> 1) * 64;
    int wn = (w & 1) * 32;

    int colTile = blockIdx.x * 64;
    int rowTile = blockIdx.y * 128;
    int b = rowTile >> 10;
    int lbase = rowTile & 1023;

    // smem bases (bf16 units): A[stage][hi/lo], B[stage][hi/lo]
    uint32_t base = smem_u32(sm);
    uint32_t aB[2][2], bB[2][2];
#pragma unroll
    for (int s = 0; s < 2; s++)
#pragma unroll
        for (int hl = 0; hl < 2; hl++) {
            aB[s][hl] = base + (uint32_t)((s * 2 + hl) * A_MAT) * 2;
            bB[s][hl] = base + (uint32_t)(4 * A_MAT + (s * 2 + hl) * B_MAT) * 2;
        }

    const __nv_bfloat16* whi = g_whi[wsel];
    const __nv_bfloat16* wlo = g_wlo[wsel];

    float acc[4][4][4];
#pragma unroll
    for (int mt = 0; mt < 4; mt++)
#pragma unroll
        for (int nt = 0; nt < 4; nt++)
#pragma unroll
            for (int r = 0; r < 4; r++) acc[mt][nt][r] = 0.f;

    int lrow = lane & 15;
    int lhalf = (lane >> 4) * 8;

    // ---- staging helpers ----
    auto stageA = [&](int k0, int s) {
        for (int v = tid; v < A_ROWS * 4; v += 128) {   // 130 rows x 4 uint4
            int row = v >> 2;
            int c8 = (v & 3) << 3;
            int l = lbase + row - 1;
            int nb = (l >= 0 && l < Lq) ? 16 : 0;
            int lc = l < 0 ? 0 : (l > Lq - 1 ? Lq - 1 : l);
            size_t g = ((size_t)(b << 10) + lc) * Dm + k0 + c8;
            uint32_t doff = (uint32_t)(row * SSTR + c8) * 2;
            cp_async16(aB[s][0] + doff, g_xhi + g, nb);
            cp_async16(aB[s][1] + doff, g_xlo + g, nb);
        }
    };
    auto stageB = [&](int k0, int t, int s) {
        const __nv_bfloat16* wh = whi + ((size_t)t << 20);
        const __nv_bfloat16* wl = wlo + ((size_t)t << 20);
        for (int v = tid; v < 256; v += 128) {          // 64 rows x 4 uint4
            int row = v >> 2;
            int c8 = (v & 3) << 3;
            size_t gw = (size_t)(colTile + row) * Dm + k0 + c8;
            uint32_t doff = (uint32_t)(row * SSTR + c8) * 2;
            cp_async16(bB[s][0] + doff, wh + gw, 16);
            cp_async16(bB[s][1] + doff, wl + gw, 16);
        }
    };

    // ---- prologue: loads for iteration 0 ----
    stageA(0, 0);
    stageB(0, 0, 0);
    CP_COMMIT();

    // iteration it = (k-chunk, tap): k0 = (it/3)*32, t = it%3
    for (int it = 0; it < 96; ++it) {
        int t = it - (it / 3) * 3;
        int aCur = (it / 3) & 1;
        int bCur = it & 1;

        // issue loads for it+1
        int itn = it + 1;
        if (itn < 96) {
            int kn = itn / 3;
            int tn = itn - kn * 3;
            if (tn == 0) stageA(kn * 32, kn & 1);
            stageB(kn * 32, tn, itn & 1);
        }
        CP_COMMIT();
        CP_WAIT1();          // loads for `it` complete
        __syncthreads();

        // ---- compute tap t from A[aCur] (+t row offset), B[bCur] ----
#pragma unroll
        for (int ks = 0; ks < 32; ks += 16) {
            uint32_t a_hi[4][4], a_lo[4][4];
#pragma unroll
            for (int mt = 0; mt < 4; mt++) {
                uint32_t off = (uint32_t)((wm + mt * 16 + lrow + t) * SSTR + ks + lhalf) * 2;
                ldsm_x4(a_hi[mt], aB[aCur][0] + off);
                ldsm_x4(a_lo[mt], aB[aCur][1] + off);
            }
            uint32_t b_hi[4][2], b_lo[4][2];
#pragma unroll
            for (int p = 0; p < 2; p++) {
                uint32_t off = (uint32_t)((wn + p * 16 + lrow) * SSTR + ks + lhalf) * 2;
                uint32_t q[4];
                ldsm_x4(q, bB[bCur][0] + off);
                b_hi[2 * p][0] = q[0]; b_hi[2 * p][1] = q[2];
                b_hi[2 * p + 1][0] = q[1]; b_hi[2 * p + 1][1] = q[3];
                ldsm_x4(q, bB[bCur][1] + off);
                b_lo[2 * p][0] = q[0]; b_lo[2 * p][1] = q[2];
                b_lo[2 * p + 1][0] = q[1]; b_lo[2 * p + 1][1] = q[3];
            }
#pragma unroll
            for (int mt = 0; mt < 4; mt++)
#pragma unroll
                for (int nt = 0; nt < 4; nt++) {
                    mma16816(acc[mt][nt], a_hi[mt], b_hi[nt][0], b_hi[nt][1]);
                    mma16816(acc[mt][nt], a_hi[mt], b_lo[nt][0], b_lo[nt][1]);
                    mma16816(acc[mt][nt], a_lo[mt], b_hi[nt][0], b_hi[nt][1]);
                }
        }
        __syncthreads();     // all warps done reading before next writes land
    }

    // ---- epilogue ----
    if (ysel < 3) {
        __nv_bfloat16 *yh, *yl;
        if (ysel == 0)      { yh = g_qhi; yl = g_qlo; }
        else if (ysel == 1) { yh = g_khi; yl = g_klo; }
        else                { yh = g_vhi; yl = g_vlo; }
#pragma unroll
        for (int nt = 0; nt < 4; nt++) {
            int n0 = colTile + wn + nt * 8 + (lane & 3) * 2;
            float b0 = bias[n0], b1 = bias[n0 + 1];
#pragma unroll
            for (int mt = 0; mt < 4; mt++) {
                int m0 = rowTile + wm + mt * 16 + (lane >> 2);
                float* c = acc[mt][nt];
                __nv_bfloat16 h0, l0, h1, l1;
                split_bf16(c[0] + b0, h0, l0);
                split_bf16(c[1] + b1, h1, l1);
                *reinterpret_cast<__nv_bfloat162*>(yh + (size_t)m0 * Dm + n0) = __nv_bfloat162(h0, h1);
                *reinterpret_cast<__nv_bfloat162*>(yl + (size_t)m0 * Dm + n0) = __nv_bfloat162(l0, l1);
                split_bf16(c[2] + b0, h0, l0);
                split_bf16(c[3] + b1, h1, l1);
                *reinterpret_cast<__nv_bfloat162*>(yh + (size_t)(m0 + 8) * Dm + n0) = __nv_bfloat162(h0, h1);
                *reinterpret_cast<__nv_bfloat162*>(yl + (size_t)(m0 + 8) * Dm + n0) = __nv_bfloat162(l0, l1);
            }
        }
    } else {
#pragma unroll
        for (int nt = 0; nt < 4; nt++) {
            int n0 = colTile + wn + nt * 8 + (lane & 3) * 2;
            float b0 = bias[n0], b1 = bias[n0 + 1];
#pragma unroll
            for (int mt = 0; mt < 4; mt++) {
                int m0 = rowTile + wm + mt * 16 + (lane >> 2);
                float* c = acc[mt][nt];
                *reinterpret_cast<float2*>(yext + (size_t)m0 * Dm + n0) =
                    make_float2(c[0] + b0, c[1] + b1);
                *reinterpret_cast<float2*>(yext + (size_t)(m0 + 8) * Dm + n0) =
                    make_float2(c[2] + b0, c[3] + b1);
            }
        }
    }
}

// ---------------- scores on tensor cores ----------------
__global__ __launch_bounds__(128) void scores_mma(
    const float* __restrict__ am, const void* __restrict__ kpm)
{
    __shared__ __nv_bfloat16 sQh[128][SSTR];
    __shared__ __nv_bfloat16 sQl[128][SSTR];
    __shared__ __nv_bfloat16 sKh[128][SSTR];
    __shared__ __nv_bfloat16 sKl[128][SSTR];

    int bh = blockIdx.z, b = bh >> 4, h = bh & 15;
    int i0 = blockIdx.y * 128, j0 = blockIdx.x * 128;
    const __nv_bfloat16* qh = g_qhi + ((size_t)(b << 10) + i0) * Dm + h * HD;
    const __nv_bfloat16* ql = g_qlo + ((size_t)(b << 10) + i0) * Dm + h * HD;
    const __nv_bfloat16* kh = g_khi + ((size_t)(b << 10) + j0) * Dm + h * HD;
    const __nv_bfloat16* kl = g_klo + ((size_t)(b << 10) + j0) * Dm + h * HD;

    int tid = threadIdx.x, lane = tid & 31, w = tid >> 5;
    int wm = (w >> 1) * 64, wn = (w & 1) * 64;
    int lrow = lane & 15, lhalf = (lane >> 4) * 8;

    float acc[4][8][4];
#pragma unroll
    for (int mt = 0; mt < 4; mt++)
#pragma unroll
        for (int nt = 0; nt < 8; nt++)
#pragma unroll
            for (int r = 0; r < 4; r++) acc[mt][nt][r] = 0.f;

    uint32_t bQh = smem_u32(&sQh[0][0]), bQl = smem_u32(&sQl[0][0]);
    uint32_t bKh = smem_u32(&sKh[0][0]), bKl = smem_u32(&sKl[0][0]);

    for (int k0 = 0; k0 < HD; k0 += 32) {
        __syncthreads();
#pragma unroll
        for (int vv = 0; vv < 4; ++vv) {
            int v = tid + vv * 128;
            int row = v >> 2;
            int c8 = (v & 3) << 3;
            size_t off = (size_t)row * Dm + k0 + c8;
            *reinterpret_cast<uint4*>(&sQh[row][c8]) = *reinterpret_cast<const uint4*>(qh + off);
            *reinterpret_cast<uint4*>(&sQl[row][c8]) = *reinterpret_cast<const uint4*>(ql + off);
            *reinterpret_cast<uint4*>(&sKh[row][c8]) = *reinterpret_cast<const uint4*>(kh + off);
            *reinterpret_cast<uint4*>(&sKl[row][c8]) = *reinterpret_cast<const uint4*>(kl + off);
        }
        __syncthreads();

#pragma unroll
        for (int ks = 0; ks < 32; ks += 16) {
            uint32_t ah[4][4], al[4][4];
#pragma unroll
            for (int mt = 0; mt < 4; mt++) {
                uint32_t off = (uint32_t)((wm + mt * 16 + lrow) * SSTR + ks + lhalf) * 2;
                ldsm_x4(ah[mt], bQh + off);
                ldsm_x4(al[mt], bQl + off);
            }
#pragma unroll
            for (int p = 0; p < 4; p++) {
                uint32_t off = (uint32_t)((wn + p * 16 + lrow) * SSTR + ks + lhalf) * 2;
                uint32_t kh4[4], kl4[4];
                ldsm_x4(kh4, bKh + off);
                ldsm_x4(kl4, bKl + off);
#pragma unroll
                for (int mt = 0; mt < 4; mt++) {
                    mma16816(acc[mt][2 * p],     ah[mt], kh4[0], kh4[2]);
                    mma16816(acc[mt][2 * p],     ah[mt], kl4[0], kl4[2]);
                    mma16816(acc[mt][2 * p],     al[mt], kh4[0], kh4[2]);
                    mma16816(acc[mt][2 * p + 1], ah[mt], kh4[1], kh4[3]);
                    mma16816(acc[mt][2 * p + 1], ah[mt], kl4[1], kl4[3]);
                    mma16816(acc[mt][2 * p + 1], al[mt], kh4[1], kh4[3]);
                }
            }
        }
    }

    int mword = g_mask_is_word;
    float* srow = g_scores + (size_t)bh * Lq * Lq;
    const float scale = 0.125f;
#pragma unroll
    for (int nt = 0; nt < 8; nt++) {
        int n0 = j0 + wn + nt * 8 + (lane & 3) * 2;
        bool mk0 = mword ? (((const int*)kpm)[b * Lq + n0] != 0)
                         : (((const unsigned char*)kpm)[b * Lq + n0] != 0);
        bool mk1 = mword ? (((const int*)kpm)[b * Lq + n0 + 1] != 0)
                         : (((const unsigned char*)kpm)[b * Lq + n0 + 1] != 0);
#pragma unroll
        for (int mt = 0; mt < 4; mt++) {
            float* c = acc[mt][nt];
            int m0 = i0 + wm + mt * 16 + (lane >> 2);
            float2 a0 = *reinterpret_cast<const float2*>(am + (size_t)m0 * Lq + n0);
            *reinterpret_cast<float2*>(srow + (size_t)m0 * Lq + n0) =
                make_float2(mk0 ? -INFINITY : c[0] * scale + a0.x,
                            mk1 ? -INFINITY : c[1] * scale + a0.y);
            int m1 = m0 + 8;
            float2 a1 = *reinterpret_cast<const float2*>(am + (size_t)m1 * Lq + n0);
            *reinterpret_cast<float2*>(srow + (size_t)m1 * Lq + n0) =
                make_float2(mk0 ? -INFINITY : c[2] * scale + a1.x,
                            mk1 ? -INFINITY : c[3] * scale + a1.y);
        }
    }
}

// ---------------- row softmax -> split bf16 attn ----------------
__global__ __launch_bounds__(256) void softmax_rows() {
    size_t row = blockIdx.x;
    const float* p = g_scores + row * Lq;
    __nv_bfloat16* ph = g_phi + row * Lq;
    __nv_bfloat16* pl = g_plo + row * Lq;
    int tid = threadIdx.x;
    __shared__ float red[256];

    float v[4];
    float m = -INFINITY;
#pragma unroll
    for (int c = 0; c < 4; c++) {
        v[c] = p[tid + c * 256];
        m = fmaxf(m, v[c]);
    }
    red[tid] = m;
    __syncthreads();
    for (int s = 128; s > 0; s >>= 1) {
        if (tid < s) red[tid] = fmaxf(red[tid], red[tid + s]);
        __syncthreads();
    }
    m = red[0];
    __syncthreads();

    float sum = 0.f;
#pragma unroll
    for (int c = 0; c < 4; c++) {
        v[c] = expf(v[c] - m);
        sum += v[c];
    }
    red[tid] = sum;
    __syncthreads();
    for (int s = 128; s > 0; s >>= 1) {
        if (tid < s) red[tid] += red[tid + s];
        __syncthreads();
    }
    float inv = 1.f / red[0];
#pragma unroll
    for (int c = 0; c < 4; c++) {
        float pv = v[c] * inv;
        __nv_bfloat16 h, l;
        split_bf16(pv, h, l);
        ph[tid + c * 256] = h;
        pl[tid + c * 256] = l;
    }
}

// ---------------- PV on tensor cores ----------------
#define VSTR 72

__global__ __launch_bounds__(128) void pv_mma() {
    __shared__ __nv_bfloat16 sPh[128][SSTR];
    __shared__ __nv_bfloat16 sPl[128][SSTR];
    __shared__ __nv_bfloat16 sVh[32][VSTR];
    __shared__ __nv_bfloat16 sVl[32][VSTR];

    int bh = blockIdx.y, b = bh >> 4, h = bh & 15;
    int i0 = blockIdx.x * 128;
    const __nv_bfloat16* ph = g_phi + ((size_t)bh * Lq + i0) * Lq;
    const __nv_bfloat16* pl = g_plo + ((size_t)bh * Lq + i0) * Lq;
    const __nv_bfloat16* vh = g_vhi + ((size_t)(b << 10)) * Dm + h * HD;
    const __nv_bfloat16* vl = g_vlo + ((size_t)(b << 10)) * Dm + h * HD;

    int tid = threadIdx.x, lane = tid & 31, w = tid >> 5;
    int wm = (w >> 1) * 64, wn = (w & 1) * 32;
    int lrow = lane & 15, lhalf = (lane >> 4) * 8;

    float acc[4][4][4];
#pragma unroll
    for (int mt = 0; mt < 4; mt++)
#pragma unroll
        for (int nt = 0; nt < 4; nt++)
#pragma unroll
            for (int r = 0; r < 4; r++) acc[mt][nt][r] = 0.f;

    uint32_t bPh = smem_u32(&sPh[0][0]), bPl = smem_u32(&sPl[0][0]);
    uint32_t bVh = smem_u32(&sVh[0][0]), bVl = smem_u32(&sVl[0][0]);

    for (int k0 = 0; k0 < Lq; k0 += 32) {
        __syncthreads();
#pragma unroll
        for (int vv = 0; vv < 4; ++vv) {
            int v = tid + vv * 128;
            int row = v >> 2;
            int c8 = (v & 3) << 3;
            size_t off = (size_t)row * Lq + k0 + c8;
            *reinterpret_cast<uint4*>(&sPh[row][c8]) = *reinterpret_cast<const uint4*>(ph + off);
            *reinterpret_cast<uint4*>(&sPl[row][c8]) = *reinterpret_cast<const uint4*>(pl + off);
        }
#pragma unroll
        for (int vv = 0; vv < 2; ++vv) {
            int v = tid + vv * 128;
            int row = v >> 3;
            int c8 = (v & 7) << 3;
            size_t off = (size_t)(k0 + row) * Dm + c8;
            *reinterpret_cast<uint4*>(&sVh[row][c8]) = *reinterpret_cast<const uint4*>(vh + off);
            *reinterpret_cast<uint4*>(&sVl[row][c8]) = *reinterpret_cast<const uint4*>(vl + off);
        }
        __syncthreads();

#pragma unroll
        for (int ks = 0; ks < 32; ks += 16) {
            uint32_t ah[4][4], al[4][4];
#pragma unroll
            for (int mt = 0; mt < 4; mt++) {
                uint32_t off = (uint32_t)((wm + mt * 16 + lrow) * SSTR + ks + lhalf) * 2;
                ldsm_x4(ah[mt], bPh + off);
                ldsm_x4(al[mt], bPl + off);
            }
#pragma unroll
            for (int p = 0; p < 2; p++) {
                uint32_t off = (uint32_t)((ks + lrow) * VSTR + wn + p * 16 + lhalf) * 2;
                uint32_t vh4[4], vl4[4];
                ldsm_x4_t(vh4, bVh + off);
                ldsm_x4_t(vl4, bVl + off);
#pragma unroll
                for (int mt = 0; mt < 4; mt++) {
                    mma16816(acc[mt][2 * p],     ah[mt], vh4[0], vh4[1]);
                    mma16816(acc[mt][2 * p],     ah[mt], vl4[0], vl4[1]);
                    mma16816(acc[mt][2 * p],     al[mt], vh4[0], vh4[1]);
                    mma16816(acc[mt][2 * p + 1], ah[mt], vh4[2], vh4[3]);
                    mma16816(acc[mt][2 * p + 1], ah[mt], vl4[2], vl4[3]);
                    mma16816(acc[mt][2 * p + 1], al[mt], vh4[2], vh4[3]);
                }
            }
        }
    }

    float* cb = g_ctx + ((size_t)(b << 10)) * Dm + h * HD;
#pragma unroll
    for (int nt = 0; nt < 4; nt++) {
        int n0 = wn + nt * 8 + (lane & 3) * 2;
#pragma unroll
        for (int mt = 0; mt < 4; mt++) {
            int m0 = i0 + wm + mt * 16 + (lane >> 2);
            float* c = acc[mt][nt];
            *reinterpret_cast<float2*>(cb + (size_t)m0 * Dm + n0) = make_float2(c[0], c[1]);
            *reinterpret_cast<float2*>(cb + (size_t)(m0 + 8) * Dm + n0) = make_float2(c[2], c[3]);
        }
    }
}

// ---------------- launch ----------------
extern "C" void kernel_launch(void* const* d_in, const int* in_sizes, int n_in,
                              void* d_out, int out_size) {
    const float* qkv[3] = {nullptr, nullptr, nullptr};
    const float* ws[4]  = {nullptr, nullptr, nullptr, nullptr};
    const float* bs[4]  = {nullptr, nullptr, nullptr, nullptr};
    const void*  kpm = nullptr;
    const float* am  = nullptr;
    int nqkv = 0, nw = 0, nb = 0;
    for (int i = 0; i < n_in; ++i) {
        int sz = in_sizes[i];
        if (sz == Bsz * Lq * Dm)           { if (nqkv < 3) qkv[nqkv++] = (const float*)d_in[i]; }
        else if (sz == 3 * Dm * Dm)        { if (nw < 4)   ws[nw++]    = (const float*)d_in[i]; }
        else if (sz == Dm)                 { if (nb < 4)   bs[nb++]    = (const float*)d_in[i]; }
        else if (sz == Bsz * Lq)           { kpm = d_in[i]; }
        else if (sz == Lq * Lq)            { am  = (const float*)d_in[i]; }
    }
    float* out = (float*)d_out;

    cudaFuncSetAttribute(conv_mma, cudaFuncAttributeMaxDynamicSharedMemorySize, CONV_SMEM);

    detect_mask<<<1, 256>>>((const unsigned char*)kpm);

    for (int s = 0; s < 4; ++s)
        prep_w<<<3 * Dm * Dm / 256, 256>>>(ws[s], s);

    dim3 cg(Dm / 64, Bsz * Lq / 128);     // (16, 32)
    const int PX_GRID = Bsz * Lq * Dm / 4 / 256;

    prep_x<<<PX_GRID, 256>>>(qkv[0], 0);
    conv_mma<<<cg, 128, CONV_SMEM>>>(bs[0], nullptr, 0, 0);
    prep_x<<<PX_GRID, 256>>>(qkv[1], 0);
    conv_mma<<<cg, 128, CONV_SMEM>>>(bs[1], nullptr, 1, 1);
    prep_x<<<PX_GRID, 256>>>(qkv[2], 0);
    conv_mma<<<cg, 128, CONV_SMEM>>>(bs[2], nullptr, 2, 2);

    scores_mma<<<dim3(Lq / 128, Lq / 128, Bsz * NH), 128>>>(am, kpm);
    softmax_rows<<<Bsz * NH * Lq, 256>>>();
    pv_mma<<<dim3(Lq / 128, Bsz * NH), 128>>>();

    prep_x<<<PX_GRID, 256>>>(nullptr, 1);
    conv_mma<<<cg, 128, CONV_SMEM>>>(bs[3], out, 3, 3);
}